// round 6
// baseline (speedup 1.0000x reference)
#include <cuda_runtime.h>
#include <cuda_bf16.h>
#include <stdint.h>
#include <math.h>

// Problem constants
#define C_DIM 1536
#define L_Q   2400
#define L_KV  512
#define NH    12
#define HD    128
#define FF_DIM 8960
#define EPS   1e-6f

// ---------------- device scratch ----------------
__device__ __align__(256) float g_em[6 * C_DIM];
__device__ __align__(256) float g_q [L_Q * C_DIM];
__device__ __align__(256) float g_k [L_Q * C_DIM];
__device__ __align__(256) float g_v [L_Q * C_DIM];
__device__ __align__(256) float g_t [L_Q * C_DIM];
__device__ __align__(256) float g_s [NH * L_Q * L_Q];          // fp32 scores
__device__ __align__(256) unsigned short g_hh[L_Q * C_DIM], g_hl[L_Q * C_DIM];
__device__ __align__(256) unsigned short g_qh[L_Q * C_DIM], g_ql[L_Q * C_DIM];
__device__ __align__(256) unsigned short g_kh[L_Q * C_DIM], g_kl[L_Q * C_DIM];
__device__ __align__(256) unsigned short g_vth[C_DIM * L_Q], g_vtl[C_DIM * L_Q];
__device__ __align__(256) unsigned short g_yh[L_Q * C_DIM], g_yl[L_Q * C_DIM];
__device__ __align__(256) unsigned short g_oh[L_Q * C_DIM], g_ol[L_Q * C_DIM];
__device__ __align__(256) unsigned short g_cxh[L_KV * C_DIM], g_cxl[L_KV * C_DIM];
__device__ __align__(256) unsigned short g_ph[NH * L_Q * L_Q], g_pl[NH * L_Q * L_Q];
__device__ __align__(256) unsigned short g_ffh[L_Q * FF_DIM], g_ffl[L_Q * FF_DIM];
__device__ __align__(256) unsigned short g_wh[FF_DIM * C_DIM], g_wl[FF_DIM * C_DIM];

// ---------------- helpers ----------------
__device__ __forceinline__ float block_reduce(float v, float* sh, bool is_max) {
    __syncthreads();
    int lane = threadIdx.x & 31, warp = threadIdx.x >> 5;
    #pragma unroll
    for (int o = 16; o > 0; o >>= 1) {
        float other = __shfl_down_sync(0xffffffffu, v, o);
        v = is_max ? fmaxf(v, other) : v + other;
    }
    if (lane == 0) sh[warp] = v;
    __syncthreads();
    int nw = blockDim.x >> 5;
    if (warp == 0) {
        v = (lane < nw) ? sh[lane] : (is_max ? -INFINITY : 0.f);
        #pragma unroll
        for (int o = 16; o > 0; o >>= 1) {
            float other = __shfl_down_sync(0xffffffffu, v, o);
            v = is_max ? fmaxf(v, other) : v + other;
        }
        if (lane == 0) sh[0] = v;
    }
    __syncthreads();
    return sh[0];
}

__device__ __forceinline__ float gelu_tanh(float v) {
    float v3 = v * v * v;
    return 0.5f * v * (1.f + tanhf(0.7978845608028654f * (v + 0.044715f * v3)));
}

static __device__ __forceinline__ void split_bf16(float v, unsigned short& h, unsigned short& l) {
    __nv_bfloat16 hb = __float2bfloat16_rn(v);
    float r = v - __bfloat162float(hb);
    __nv_bfloat16 lb = __float2bfloat16_rn(r);
    h = *reinterpret_cast<unsigned short*>(&hb);
    l = *reinterpret_cast<unsigned short*>(&lb);
}

// ---------------- elementwise / norm kernels ----------------
__global__ void em_kernel(const float* __restrict__ e, const float* __restrict__ mod,
                          float* __restrict__ em) {
    int i = blockIdx.x * blockDim.x + threadIdx.x;
    if (i < 6 * C_DIM) em[i] = e[i] + mod[i];
}

__global__ void ln_mod_split_kernel(const float* __restrict__ x, const float* __restrict__ e0,
                                    const float* __restrict__ e1,
                                    unsigned short* __restrict__ oh, unsigned short* __restrict__ ol) {
    __shared__ float sh[32];
    long long row = blockIdx.x;
    const float* xr = x + row * C_DIM;
    float s = 0.f, s2 = 0.f;
    for (int c = threadIdx.x; c < C_DIM; c += blockDim.x) {
        float v = xr[c];
        s += v; s2 += v * v;
    }
    float S  = block_reduce(s,  sh, false);
    float S2 = block_reduce(s2, sh, false);
    float m   = S  * (1.f / C_DIM);
    float var = S2 * (1.f / C_DIM) - m * m;
    float inv = rsqrtf(var + EPS);
    for (int c = threadIdx.x; c < C_DIM; c += blockDim.x) {
        float v = e0[c] + (xr[c] - m) * inv * (1.f + e1[c]);
        unsigned short h, l; split_bf16(v, h, l);
        oh[row * C_DIM + c] = h;
        ol[row * C_DIM + c] = l;
    }
}

// RMS + RoPE + split, one pass (self-attn q/k)
__global__ void rms_rope_split_kernel(const float* __restrict__ x, const float* __restrict__ w,
                                      const float* __restrict__ freqs,
                                      unsigned short* __restrict__ dh, unsigned short* __restrict__ dl) {
    __shared__ float sh[32];
    int row = blockIdx.x;
    const float* xr = x + (long long)row * C_DIM;
    float s2 = 0.f;
    for (int c = threadIdx.x; c < C_DIM; c += blockDim.x) {
        float v = xr[c]; s2 += v * v;
    }
    float S2 = block_reduce(s2, sh, false);
    float inv = rsqrtf(S2 * (1.f / C_DIM) + EPS);
    int f  = row / 1200;
    int rm = row % 1200;
    int hh = rm / 40;
    int ww = rm % 40;
    for (int p = threadIdx.x; p < NH * 64; p += blockDim.x) {
        int n = p >> 6, j = p & 63;
        int pos = (j < 22) ? f : ((j < 43) ? hh : ww);
        float cs = freqs[(pos * 64 + j) * 2 + 0];
        float sn = freqs[(pos * 64 + j) * 2 + 1];
        int c = n * HD + 2 * j;
        float a = xr[c] * inv * w[c];
        float b = xr[c + 1] * inv * w[c + 1];
        float o0 = a * cs - b * sn;
        float o1 = a * sn + b * cs;
        unsigned short h0, l0, h1, l1;
        split_bf16(o0, h0, l0); split_bf16(o1, h1, l1);
        long long o = (long long)row * C_DIM + c;
        dh[o] = h0; dl[o] = l0;
        dh[o + 1] = h1; dl[o + 1] = l1;
    }
}

// RMS + split (cross-attn q/k, no rope)
__global__ void rms_split_kernel(const float* __restrict__ x, const float* __restrict__ w,
                                 unsigned short* __restrict__ dh, unsigned short* __restrict__ dl) {
    __shared__ float sh[32];
    long long row = blockIdx.x;
    const float* xr = x + row * C_DIM;
    float s2 = 0.f;
    for (int c = threadIdx.x; c < C_DIM; c += blockDim.x) {
        float v = xr[c]; s2 += v * v;
    }
    float S2 = block_reduce(s2, sh, false);
    float inv = rsqrtf(S2 * (1.f / C_DIM) + EPS);
    for (int c = threadIdx.x; c < C_DIM; c += blockDim.x) {
        float v = xr[c] * inv * w[c];
        unsigned short h, l; split_bf16(v, h, l);
        dh[row * C_DIM + c] = h;
        dl[row * C_DIM + c] = l;
    }
}

__global__ void conv_split_kernel(const float* __restrict__ src, long long n,
                                  unsigned short* __restrict__ dh, unsigned short* __restrict__ dl) {
    long long i = (long long)blockIdx.x * blockDim.x + threadIdx.x;
    if (i < n) {
        unsigned short h, l; split_bf16(src[i], h, l);
        dh[i] = h; dl[i] = l;
    }
}

// [R, Ccol] fp32 -> [Ccol, R] bf16 hi/lo
__global__ void transpose_split_kernel(const float* __restrict__ src, int R, int Ccol,
                                       unsigned short* __restrict__ dh, unsigned short* __restrict__ dl) {
    __shared__ float tile[32][33];
    int bx = blockIdx.x, by = blockIdx.y;
    int tx = threadIdx.x, ty = threadIdx.y;  // 32 x 8
    #pragma unroll
    for (int i = 0; i < 4; i++) {
        int r = by * 32 + ty + i * 8;
        tile[ty + i * 8][tx] = src[(long long)r * Ccol + bx * 32 + tx];
    }
    __syncthreads();
    #pragma unroll
    for (int i = 0; i < 4; i++) {
        int ro = bx * 32 + ty + i * 8;
        int co = by * 32 + tx;
        float v = tile[tx][ty + i * 8];
        unsigned short h, l; split_bf16(v, h, l);
        dh[(long long)ro * R + co] = h;
        dl[(long long)ro * R + co] = l;
    }
}

__global__ void softmax_split_kernel(const float* __restrict__ s, int lk,
                                     unsigned short* __restrict__ ph, unsigned short* __restrict__ pl) {
    __shared__ float sh[32];
    long long row = blockIdx.x;
    const float* p = s + row * (long long)lk;
    float mx = -INFINITY;
    for (int i = threadIdx.x; i < lk; i += blockDim.x) mx = fmaxf(mx, p[i]);
    mx = block_reduce(mx, sh, true);
    float sum = 0.f;
    for (int i = threadIdx.x; i < lk; i += blockDim.x) sum += __expf(p[i] - mx);
    sum = block_reduce(sum, sh, false);
    float inv = 1.f / sum;
    for (int i = threadIdx.x; i < lk; i += blockDim.x) {
        float v = __expf(p[i] - mx) * inv;
        unsigned short h, l; split_bf16(v, h, l);
        ph[row * (long long)lk + i] = h;
        pl[row * (long long)lk + i] = l;
    }
}

__global__ void residual_mul_conv_kernel(const float* __restrict__ xin, const float* __restrict__ t,
                                         const float* __restrict__ ecol, float* __restrict__ out,
                                         unsigned short* __restrict__ oh, unsigned short* __restrict__ ol) {
    long long i = (long long)blockIdx.x * blockDim.x + threadIdx.x;
    if (i < (long long)L_Q * C_DIM) {
        float v = xin[i] + t[i] * ecol[i % C_DIM];
        out[i] = v;
        unsigned short h, l; split_bf16(v, h, l);
        oh[i] = h; ol[i] = l;
    }
}

__global__ void add_inplace_kernel(float* __restrict__ x, const float* __restrict__ t) {
    long long i = (long long)blockIdx.x * blockDim.x + threadIdx.x;
    if (i < (long long)L_Q * C_DIM) x[i] += t[i];
}

__global__ void addmul_inplace_kernel(float* __restrict__ x, const float* __restrict__ t,
                                      const float* __restrict__ ecol) {
    long long i = (long long)blockIdx.x * blockDim.x + threadIdx.x;
    if (i < (long long)L_Q * C_DIM) x[i] += t[i] * ecol[i % C_DIM];
}

// =====================================================================
// Split-bf16 HMMA GEMM v3: 128x128x32 tiles, 3-stage cp.async, 2 CTAs/SM.
//   A: [M,K] bf16 hi/lo row-major.  B: [N,K] bf16 hi/lo K-major.
// =====================================================================
#define STAGES 3
#define STG 32768
#define SA_H 0
#define SA_L 8192
#define SB_H 16384
#define SB_L 24576
#define HG_SMEM (STAGES * STG)   // 98304

static __device__ __forceinline__ uint32_t smem_u32(const void* p) {
    uint32_t r;
    asm("{ .reg .u64 t; cvta.to.shared.u64 t, %1; cvt.u32.u64 %0, t; }" : "=r"(r) : "l"(p));
    return r;
}
// 64B-row swizzled smem addr for (row 0..127, ch 0..3); conflict-free ldmatrix
static __device__ __forceinline__ uint32_t saddr(int row, int ch) {
    return (uint32_t)(((row >> 1) << 7) +
                      (((((row & 1) << 2) | ch) ^ ((row >> 1) & 3)) << 4));
}
static __device__ __forceinline__ void cpa16(uint32_t s, const void* g, uint32_t sz) {
    asm volatile("cp.async.cg.shared.global [%0], [%1], 16, %2;" :: "r"(s), "l"(g), "r"(sz));
}
static __device__ __forceinline__ void cpa_commit() {
    asm volatile("cp.async.commit_group;");
}
static __device__ __forceinline__ void cpa_wait1() {
    asm volatile("cp.async.wait_group 1;");
}
static __device__ __forceinline__ void ldm_x4(uint32_t* r, uint32_t addr) {
    asm volatile("ldmatrix.sync.aligned.m8n8.x4.shared.b16 {%0,%1,%2,%3}, [%4];"
                 : "=r"(r[0]), "=r"(r[1]), "=r"(r[2]), "=r"(r[3]) : "r"(addr));
}
static __device__ __forceinline__ void mma16816(float* c, const uint32_t* a, uint32_t b0, uint32_t b1) {
    asm volatile("mma.sync.aligned.m16n8k16.row.col.f32.bf16.bf16.f32 "
                 "{%0,%1,%2,%3}, {%4,%5,%6,%7}, {%8,%9}, {%0,%1,%2,%3};"
                 : "+f"(c[0]), "+f"(c[1]), "+f"(c[2]), "+f"(c[3])
                 : "r"(a[0]), "r"(a[1]), "r"(a[2]), "r"(a[3]), "r"(b0), "r"(b1));
}

__global__ void __launch_bounds__(256, 2)
hgemm3_kernel(const unsigned short* __restrict__ Ah, const unsigned short* __restrict__ Al,
              int lda, long long sAz,
              const unsigned short* __restrict__ Bh, const unsigned short* __restrict__ Bl,
              int ldb, long long sBz,
              float* __restrict__ Cf, unsigned short* __restrict__ Ch, unsigned short* __restrict__ Cl,
              int ldc, long long sCz,
              int M, int N, int K,
              const float* __restrict__ bias, float scale, int act) {
    extern __shared__ char smem[];
    uint32_t sbase = smem_u32(smem);

    int tid = threadIdx.x, lane = tid & 31, warp = tid >> 5;
    int wm = warp & 1, wn = warp >> 1;       // 2 x 4 warps, warp tile 64x32

    long long zz = blockIdx.z;
    Ah += zz * sAz; Al += zz * sAz;
    Bh += zz * sBz; Bl += zz * sBz;
    if (Cf) Cf += zz * sCz;
    if (Ch) { Ch += zz * sCz; Cl += zz * sCz; }

    int bm = blockIdx.y * 128;
    int bn = blockIdx.x * 128;
    int mRem = M - bm; if (mRem > 128) mRem = 128;
    int nRem = N - bn; if (nRem > 128) nRem = 128;

    int nch = K >> 5;   // K % 32 == 0 for all shapes here

    // ---- precomputed cp.async slots (2 per thread, stage-invariant) ----
    uint32_t so[2]; long long gA[2], gB[2]; uint32_t szA[2], szB[2];
    #pragma unroll
    for (int i = 0; i < 2; i++) {
        int idx = tid + i * 256;
        int row = idx >> 2, ch = idx & 3;
        so[i]  = saddr(row, ch);
        gA[i]  = (long long)(bm + row) * lda + ch * 8;
        gB[i]  = (long long)(bn + row) * ldb + ch * 8;
        szA[i] = (row < mRem) ? 16u : 0u;
        szB[i] = (row < nRem) ? 16u : 0u;
    }

    // ---- precomputed ldmatrix row terms ----
    int frow = lane & 15, fhalf = lane >> 4;
    uint32_t a_rt[4]; int a_sw[4], a_s[4];
    #pragma unroll
    for (int mi = 0; mi < 4; mi++) {
        int row = wm * 64 + mi * 16 + frow;
        a_rt[mi] = (uint32_t)((row >> 1) << 7);
        a_sw[mi] = (row & 1) << 2;
        a_s[mi]  = (row >> 1) & 3;
    }
    uint32_t b_rt[2]; int b_sw[2], b_s[2];
    #pragma unroll
    for (int nj = 0; nj < 2; nj++) {
        int row = wn * 32 + nj * 16 + frow;
        b_rt[nj] = (uint32_t)((row >> 1) << 7);
        b_sw[nj] = (row & 1) << 2;
        b_s[nj]  = (row >> 1) & 3;
    }

    float acc[4][4][4];
    #pragma unroll
    for (int mi = 0; mi < 4; mi++)
        #pragma unroll
        for (int ni = 0; ni < 4; ni++)
            #pragma unroll
            for (int q = 0; q < 4; q++) acc[mi][ni][q] = 0.f;

    auto loadStage = [&](int c) {
        uint32_t sb = sbase + (uint32_t)((c % STAGES) * STG);
        long long k0 = (long long)(c << 5);
        #pragma unroll
        for (int i = 0; i < 2; i++) {
            cpa16(sb + SA_H + so[i], Ah + gA[i] + k0, szA[i]);
            cpa16(sb + SA_L + so[i], Al + gA[i] + k0, szA[i]);
            cpa16(sb + SB_H + so[i], Bh + gB[i] + k0, szB[i]);
            cpa16(sb + SB_L + so[i], Bl + gB[i] + k0, szB[i]);
        }
    };

    loadStage(0); cpa_commit();
    if (nch > 1) loadStage(1);
    cpa_commit();

    for (int c = 0; c < nch; c++) {
        cpa_wait1();
        __syncthreads();
        uint32_t sb = sbase + (uint32_t)((c % STAGES) * STG);

        #pragma unroll
        for (int k16 = 0; k16 < 2; k16++) {
            int chl = k16 * 2 + fhalf;
            uint32_t bH[2][4], bL[2][4];
            #pragma unroll
            for (int nj = 0; nj < 2; nj++) {
                uint32_t off = b_rt[nj] + (uint32_t)((((b_sw[nj] | chl)) ^ b_s[nj]) << 4);
                ldm_x4(bH[nj], sb + SB_H + off);
                ldm_x4(bL[nj], sb + SB_L + off);
            }
            #pragma unroll
            for (int mi = 0; mi < 4; mi++) {
                uint32_t aH[4], aL[4];
                uint32_t off = a_rt[mi] + (uint32_t)((((a_sw[mi] | chl)) ^ a_s[mi]) << 4);
                ldm_x4(aH, sb + SA_H + off);
                ldm_x4(aL, sb + SA_L + off);
                #pragma unroll
                for (int nj = 0; nj < 2; nj++) {
                    mma16816(acc[mi][nj*2+0], aH, bH[nj][0], bH[nj][2]);
                    mma16816(acc[mi][nj*2+1], aH, bH[nj][1], bH[nj][3]);
                    mma16816(acc[mi][nj*2+0], aH, bL[nj][0], bL[nj][2]);
                    mma16816(acc[mi][nj*2+1], aH, bL[nj][1], bL[nj][3]);
                    mma16816(acc[mi][nj*2+0], aL, bH[nj][0], bH[nj][2]);
                    mma16816(acc[mi][nj*2+1], aL, bH[nj][1], bH[nj][3]);
                }
            }
        }
        if (c + 2 < nch) loadStage(c + 2);
        cpa_commit();
    }

    // ---- epilogue ----
    int row0 = lane >> 2;
    int col0 = (lane & 3) * 2;
    #pragma unroll
    for (int mi = 0; mi < 4; mi++) {
        #pragma unroll
        for (int ni = 0; ni < 4; ni++) {
            int gn = bn + wn * 32 + ni * 8 + col0;
            if (gn >= N) continue;
            float b0 = 0.f, b1 = 0.f;
            if (bias) { b0 = bias[gn]; b1 = bias[gn + 1]; }
            float* cc = acc[mi][ni];
            #pragma unroll
            for (int half = 0; half < 2; half++) {
                int gm = bm + wm * 64 + mi * 16 + row0 + half * 8;
                if (gm >= M) continue;
                float v0 = cc[half * 2 + 0] * scale + b0;
                float v1 = cc[half * 2 + 1] * scale + b1;
                if (act == 1) { v0 = gelu_tanh(v0); v1 = gelu_tanh(v1); }
                long long o = (long long)gm * ldc + gn;
                if (Cf) *reinterpret_cast<float2*>(Cf + o) = make_float2(v0, v1);
                if (Ch) {
                    unsigned short h0, l0, h1, l1;
                    split_bf16(v0, h0, l0); split_bf16(v1, h1, l1);
                    *reinterpret_cast<ushort2*>(Ch + o) = make_ushort2(h0, h1);
                    *reinterpret_cast<ushort2*>(Cl + o) = make_ushort2(l0, l1);
                }
            }
        }
    }
}

// ---------------- host ----------------
static void hgemm3(const unsigned short* Ah, const unsigned short* Al, int lda, long long sAz,
                   const unsigned short* Bh, const unsigned short* Bl, int ldb, long long sBz,
                   float* Cf, unsigned short* Ch, unsigned short* Cl, int ldc, long long sCz,
                   int M, int N, int K, int Z, const float* bias, float scale, int act) {
    dim3 grid((N + 127) / 128, (M + 127) / 128, Z);
    hgemm3_kernel<<<grid, 256, HG_SMEM>>>(Ah, Al, lda, sAz, Bh, Bl, ldb, sBz,
                                          Cf, Ch, Cl, ldc, sCz, M, N, K, bias, scale, act);
}

static void trsplit(const float* src, int R, int Ccol, unsigned short* dh, unsigned short* dl) {
    dim3 grid(Ccol / 32, R / 32);
    transpose_split_kernel<<<grid, dim3(32, 8)>>>(src, R, Ccol, dh, dl);
}

extern "C" void kernel_launch(void* const* d_in, const int* in_sizes, int n_in,
                              void* d_out, int out_size) {
    const float* x        = (const float*)d_in[0];
    const float* e        = (const float*)d_in[1];
    const float* context  = (const float*)d_in[2];
    const float* freqs    = (const float*)d_in[3];
    const float* modulation = (const float*)d_in[7];
    const float* sa_q_w = (const float*)d_in[8];
    const float* sa_q_b = (const float*)d_in[9];
    const float* sa_k_w = (const float*)d_in[10];
    const float* sa_k_b = (const float*)d_in[11];
    const float* sa_v_w = (const float*)d_in[12];
    const float* sa_v_b = (const float*)d_in[13];
    const float* sa_o_w = (const float*)d_in[14];
    const float* sa_o_b = (const float*)d_in[15];
    const float* sa_nq_w = (const float*)d_in[16];
    const float* sa_nk_w = (const float*)d_in[17];
    const float* ca_q_w = (const float*)d_in[18];
    const float* ca_q_b = (const float*)d_in[19];
    const float* ca_k_w = (const float*)d_in[20];
    const float* ca_k_b = (const float*)d_in[21];
    const float* ca_v_w = (const float*)d_in[22];
    const float* ca_v_b = (const float*)d_in[23];
    const float* ca_o_w = (const float*)d_in[24];
    const float* ca_o_b = (const float*)d_in[25];
    const float* ca_nq_w = (const float*)d_in[26];
    const float* ca_nk_w = (const float*)d_in[27];
    const float* ffn_w1 = (const float*)d_in[28];
    const float* ffn_b1 = (const float*)d_in[29];
    const float* ffn_w2 = (const float*)d_in[30];
    const float* ffn_b2 = (const float*)d_in[31];
    float* out = (float*)d_out;

    cudaFuncSetAttribute(hgemm3_kernel,
                         cudaFuncAttributeMaxDynamicSharedMemorySize, HG_SMEM);

    float *em, *q, *k, *v, *t, *s;
    unsigned short *hh, *hl, *qh, *ql, *kh, *kl, *vth, *vtl, *yh, *yl;
    unsigned short *oh, *ol, *cxh, *cxl, *ph, *pl, *ffh, *ffl, *wh, *wl;
    cudaGetSymbolAddress((void**)&em, g_em);
    cudaGetSymbolAddress((void**)&q,  g_q);
    cudaGetSymbolAddress((void**)&k,  g_k);
    cudaGetSymbolAddress((void**)&v,  g_v);
    cudaGetSymbolAddress((void**)&t,  g_t);
    cudaGetSymbolAddress((void**)&s,  g_s);
    cudaGetSymbolAddress((void**)&hh, g_hh);  cudaGetSymbolAddress((void**)&hl, g_hl);
    cudaGetSymbolAddress((void**)&qh, g_qh);  cudaGetSymbolAddress((void**)&ql, g_ql);
    cudaGetSymbolAddress((void**)&kh, g_kh);  cudaGetSymbolAddress((void**)&kl, g_kl);
    cudaGetSymbolAddress((void**)&vth, g_vth); cudaGetSymbolAddress((void**)&vtl, g_vtl);
    cudaGetSymbolAddress((void**)&yh, g_yh);  cudaGetSymbolAddress((void**)&yl, g_yl);
    cudaGetSymbolAddress((void**)&oh, g_oh);  cudaGetSymbolAddress((void**)&ol, g_ol);
    cudaGetSymbolAddress((void**)&cxh, g_cxh); cudaGetSymbolAddress((void**)&cxl, g_cxl);
    cudaGetSymbolAddress((void**)&ph, g_ph);  cudaGetSymbolAddress((void**)&pl, g_pl);
    cudaGetSymbolAddress((void**)&ffh, g_ffh); cudaGetSymbolAddress((void**)&ffl, g_ffl);
    cudaGetSymbolAddress((void**)&wh, g_wh);  cudaGetSymbolAddress((void**)&wl, g_wl);

    const float ascale = 0.08838834764831845f;   // 1/sqrt(128)
    const long long LC = (long long)L_Q * C_DIM;
    int eltBlocks = (int)((LC + 255) / 256);

    em_kernel<<<(6 * C_DIM + 255) / 256, 256>>>(e, modulation, em);

    // ================= self attention =================
    ln_mod_split_kernel<<<L_Q, 256>>>(x, em + 0 * C_DIM, em + 1 * C_DIM, hh, hl);
    trsplit(sa_q_w, C_DIM, C_DIM, wh, wl);
    hgemm3(hh, hl, C_DIM, 0, wh, wl, C_DIM, 0, q, nullptr, nullptr, C_DIM, 0,
           L_Q, C_DIM, C_DIM, 1, sa_q_b, 1.f, 0);
    trsplit(sa_k_w, C_DIM, C_DIM, wh, wl);
    hgemm3(hh, hl, C_DIM, 0, wh, wl, C_DIM, 0, k, nullptr, nullptr, C_DIM, 0,
           L_Q, C_DIM, C_DIM, 1, sa_k_b, 1.f, 0);
    trsplit(sa_v_w, C_DIM, C_DIM, wh, wl);
    hgemm3(hh, hl, C_DIM, 0, wh, wl, C_DIM, 0, v, nullptr, nullptr, C_DIM, 0,
           L_Q, C_DIM, C_DIM, 1, sa_v_b, 1.f, 0);
    rms_rope_split_kernel<<<L_Q, 256>>>(q, sa_nq_w, freqs, qh, ql);
    rms_rope_split_kernel<<<L_Q, 256>>>(k, sa_nk_w, freqs, kh, kl);
    trsplit(v, L_Q, C_DIM, vth, vtl);                // V^T [C, L]
    hgemm3(qh, ql, C_DIM, HD, kh, kl, C_DIM, HD, s, nullptr, nullptr,
           L_Q, (long long)L_Q * L_Q, L_Q, L_Q, HD, NH, nullptr, ascale, 0);
    softmax_split_kernel<<<NH * L_Q, 256>>>(s, L_Q, ph, pl);
    hgemm3(ph, pl, L_Q, (long long)L_Q * L_Q, vth, vtl, L_Q, (long long)HD * L_Q,
           nullptr, yh, yl, C_DIM, HD, L_Q, HD, L_Q, NH, nullptr, 1.f, 0);
    trsplit(sa_o_w, C_DIM, C_DIM, wh, wl);
    hgemm3(yh, yl, C_DIM, 0, wh, wl, C_DIM, 0, t, nullptr, nullptr, C_DIM, 0,
           L_Q, C_DIM, C_DIM, 1, sa_o_b, 1.f, 0);
    residual_mul_conv_kernel<<<eltBlocks, 256>>>(x, t, em + 2 * C_DIM, out, oh, ol);

    // ================= cross attention =================
    trsplit(ca_q_w, C_DIM, C_DIM, wh, wl);
    hgemm3(oh, ol, C_DIM, 0, wh, wl, C_DIM, 0, q, nullptr, nullptr, C_DIM, 0,
           L_Q, C_DIM, C_DIM, 1, ca_q_b, 1.f, 0);
    rms_split_kernel<<<L_Q, 256>>>(q, ca_nq_w, qh, ql);
    conv_split_kernel<<<(int)(((long long)L_KV * C_DIM + 255) / 256), 256>>>(
        context, (long long)L_KV * C_DIM, cxh, cxl);
    trsplit(ca_k_w, C_DIM, C_DIM, wh, wl);
    hgemm3(cxh, cxl, C_DIM, 0, wh, wl, C_DIM, 0, k, nullptr, nullptr, C_DIM, 0,
           L_KV, C_DIM, C_DIM, 1, ca_k_b, 1.f, 0);
    rms_split_kernel<<<L_KV, 256>>>(k, ca_nk_w, kh, kl);
    trsplit(ca_v_w, C_DIM, C_DIM, wh, wl);
    hgemm3(cxh, cxl, C_DIM, 0, wh, wl, C_DIM, 0, v, nullptr, nullptr, C_DIM, 0,
           L_KV, C_DIM, C_DIM, 1, ca_v_b, 1.f, 0);
    trsplit(v, L_KV, C_DIM, vth, vtl);               // V^T [C, 512]
    hgemm3(qh, ql, C_DIM, HD, kh, kl, C_DIM, HD, s, nullptr, nullptr,
           L_KV, (long long)L_Q * L_KV, L_Q, L_KV, HD, NH, nullptr, ascale, 0);
    softmax_split_kernel<<<NH * L_Q, 256>>>(s, L_KV, ph, pl);
    hgemm3(ph, pl, L_KV, (long long)L_Q * L_KV, vth, vtl, L_KV, (long long)HD * L_KV,
           nullptr, yh, yl, C_DIM, HD, L_Q, HD, L_KV, NH, nullptr, 1.f, 0);
    trsplit(ca_o_w, C_DIM, C_DIM, wh, wl);
    hgemm3(yh, yl, C_DIM, 0, wh, wl, C_DIM, 0, t, nullptr, nullptr, C_DIM, 0,
           L_Q, C_DIM, C_DIM, 1, ca_o_b, 1.f, 0);
    add_inplace_kernel<<<eltBlocks, 256>>>(out, t);

    // ================= FFN =================
    ln_mod_split_kernel<<<L_Q, 256>>>(out, em + 3 * C_DIM, em + 4 * C_DIM, hh, hl);
    trsplit(ffn_w1, C_DIM, FF_DIM, wh, wl);
    hgemm3(hh, hl, C_DIM, 0, wh, wl, C_DIM, 0, nullptr, ffh, ffl, FF_DIM, 0,
           L_Q, FF_DIM, C_DIM, 1, ffn_b1, 1.f, 1);   // + GELU, bf16 out
    trsplit(ffn_w2, FF_DIM, C_DIM, wh, wl);
    hgemm3(ffh, ffl, FF_DIM, 0, wh, wl, FF_DIM, 0, t, nullptr, nullptr, C_DIM, 0,
           L_Q, C_DIM, FF_DIM, 1, ffn_b2, 1.f, 0);
    addmul_inplace_kernel<<<eltBlocks, 256>>>(out, t, em + 5 * C_DIM);
}